// round 9
// baseline (speedup 1.0000x reference)
#include <cuda_runtime.h>

#define N_STRUCT_MAX 16384

__device__ __align__(16) float g_cinv[N_STRUCT_MAX * 12];
__device__ __align__(16) float g_cvec[N_STRUCT_MAX * 32];

__device__ __forceinline__ float leaky(float x) { return fmaxf(x, 0.01f * x); }

__device__ __forceinline__ unsigned long long pack2(float lo, float hi) {
    unsigned long long r;
    asm("mov.b64 %0, {%1, %2};" : "=l"(r) : "f"(lo), "f"(hi));
    return r;
}
__device__ __forceinline__ void unpack2(unsigned long long v, float& lo, float& hi) {
    asm("mov.b64 {%0, %1}, %2;" : "=f"(lo), "=f"(hi) : "l"(v));
}
__device__ __forceinline__ unsigned long long fma2(unsigned long long a, unsigned long long b,
                                                   unsigned long long c) {
    unsigned long long d;
    asm("fma.rn.f32x2 %0, %1, %2, %3;" : "=l"(d) : "l"(a), "l"(b), "l"(c));
    return d;
}

// One warp per structure.
__global__ __launch_bounds__(256) void precompute_kernel(
    const float* __restrict__ cell,
    const float* __restrict__ w2a,
    const float* __restrict__ b2a,
    float* __restrict__ out, int S)
{
    __shared__ float sW[81 * 32];  // [t][j] = w2a[j*90+9+t]
    int tid = threadIdx.x;
    for (int i = tid; i < 81 * 32; i += blockDim.x) {
        int t = i >> 5, j = i & 31;
        sW[i] = w2a[j * 90 + 9 + t];
    }
    __syncthreads();

    int warpId = tid >> 5;
    int lane = tid & 31;
    int s = blockIdx.x * 8 + warpId;
    if (s >= S) return;

    float m[9];
#pragma unroll
    for (int i = 0; i < 9; i++) m[i] = __ldg(cell + s * 9 + i);

    float acc = b2a[lane];
#pragma unroll
    for (int p = 0; p < 9; p++) {
        float mp = m[p];
#pragma unroll
        for (int q = 0; q < 9; q++)
            acc = fmaf(sW[(p * 9 + q) * 32 + lane], mp * m[q], acc);
    }
    g_cvec[s * 32 + lane] = acc;

    if (lane < 6) out[s * 6 + lane] = 0.f;

    if (lane == 0) {
        float c00 = m[4] * m[8] - m[5] * m[7];
        float c01 = m[5] * m[6] - m[3] * m[8];
        float c02 = m[3] * m[7] - m[4] * m[6];
        float det = m[0] * c00 + m[1] * c01 + m[2] * c02;
        float id = 1.f / det;
        float4* o = (float4*)(g_cinv + s * 12);
        float4 r0, r1, r2;
        r0.x = c00 * id;
        r0.y = (m[2] * m[7] - m[1] * m[8]) * id;
        r0.z = (m[1] * m[5] - m[2] * m[4]) * id;
        r0.w = c01 * id;
        r1.x = (m[0] * m[8] - m[2] * m[6]) * id;
        r1.y = (m[2] * m[3] - m[0] * m[5]) * id;
        r1.z = c02 * id;
        r1.w = (m[1] * m[6] - m[0] * m[7]) * id;
        r2.x = (m[0] * m[4] - m[1] * m[3]) * id;
        r2.y = 0.f; r2.z = 0.f; r2.w = 0.f;
        o[0] = r0; o[1] = r1; o[2] = r2;
    }
}

// 3 atoms per thread: crossbar amortized 3x, regs fit 4 blocks/SM.
__global__ void __launch_bounds__(128, 4) atom_kernel(
    const float* __restrict__ atom_prop, const float* __restrict__ pos,
    const int* __restrict__ batch,
    const float* __restrict__ w0, const float* __restrict__ b0,
    const float* __restrict__ w1, const float* __restrict__ b1,
    const float* __restrict__ w1n, const float* __restrict__ b1n,
    const float* __restrict__ w2a,
    const float* __restrict__ w2b, const float* __restrict__ b2b,
    const float* __restrict__ w2c, const float* __restrict__ b2c,
    float* __restrict__ out, int n)
{
    __shared__ __align__(16) float sW1t[9 * 32];   // [k][j]
    __shared__ __align__(16) float sW2t[32 * 16];  // [k][j]
    __shared__ __align__(16) float sW3t[16 * 8];   // [k][j], row padded to 8 (6 used)
    __shared__ float sSmall[64];

    int tid = threadIdx.x;
    for (int i = tid; i < 288; i += blockDim.x) {
        int k = i >> 5, j = i & 31;
        sW1t[i] = w2a[j * 90 + k];
    }
    for (int i = tid; i < 512; i += blockDim.x) {
        int k = i >> 4, j = i & 15;
        sW2t[i] = w2b[j * 32 + k];
    }
    for (int i = tid; i < 128; i += blockDim.x) {
        int k = i >> 3, j = i & 7;
        sW3t[i] = (j < 6) ? w2c[j * 16 + k] : 0.f;
    }
    if (tid < 9)        sSmall[tid] = w0[tid];
    else if (tid < 18)  sSmall[tid] = w1[tid - 9];
    else if (tid < 27)  sSmall[tid] = w1n[tid - 18];
    else if (tid < 30)  sSmall[tid] = b0[tid - 27];
    else if (tid < 33)  sSmall[tid] = b1[tid - 30];
    else if (tid < 36)  sSmall[tid] = b1n[tid - 33];
    else if (tid < 52)  sSmall[tid] = b2b[tid - 36];
    else if (tid < 60)  sSmall[tid] = (tid < 58) ? b2c[tid - 52] : 0.f;
    __syncthreads();

    const float* sw0  = sSmall;
    const float* sw1  = sSmall + 9;
    const float* sw1n = sSmall + 18;
    const float* sb0  = sSmall + 27;
    const float* sb1  = sSmall + 30;
    const float* sb1n = sSmall + 33;
    const float* sb2b = sSmall + 36;
    const float* sb2c = sSmall + 52;

    int lane = tid & 31;
    int i0 = (blockIdx.x * blockDim.x + tid) * 3;
    int nval = n - i0;
    if (nval > 3) nval = 3;
    if (nval < 0) nval = 0;

    int kk[3];
#pragma unroll
    for (int at = 0; at < 3; at++) {
        bool v = (at < nval);
        kk[at] = v ? __ldg(batch + i0 + at) : (at ? kk[at - 1] : -1);
    }
    int gk[3];
#pragma unroll
    for (int at = 0; at < 3; at++) gk[at] = kk[at] < 0 ? 0 : kk[at];

    // ---- head: per-atom 9-feature vector ----
    float x[3][9];
#pragma unroll
    for (int at = 0; at < 3; at++) {
        bool v = (at < nval);
        int idx = i0 + at;
        float P0  = v ? __ldg(pos + 3 * idx)     : 0.f;
        float P1  = v ? __ldg(pos + 3 * idx + 1) : 0.f;
        float P2  = v ? __ldg(pos + 3 * idx + 2) : 0.f;
        float A0  = v ? __ldg(atom_prop + 3 * idx)     : 0.f;
        float A1  = v ? __ldg(atom_prop + 3 * idx + 1) : 0.f;
        float A2  = v ? __ldg(atom_prop + 3 * idx + 2) : 0.f;

        const float4* civ = (const float4*)(g_cinv + gk[at] * 12);
        float4 c0 = civ[0], c1 = civ[1], c2 = civ[2];
        float ci[9] = {c0.x, c0.y, c0.z, c0.w, c1.x, c1.y, c1.z, c1.w, c2.x};
        float th[3];
#pragma unroll
        for (int e = 0; e < 3; e++) {
            float f = fmaf(P0, ci[e], fmaf(P1, ci[3 + e], P2 * ci[6 + e]));
            th[e] = f - floorf(f) - 0.5f;
        }
        x[at][0] = A0; x[at][1] = A1; x[at][2] = A2;
#pragma unroll
        for (int j = 0; j < 3; j++) {
            float a = leaky(fmaf(sw0[j*3], A0, fmaf(sw0[j*3+1], A1, fmaf(sw0[j*3+2], A2, sb0[j]))));
            float u = fmaf(sw1[j*3], th[0], fmaf(sw1[j*3+1], th[1], fmaf(sw1[j*3+2], th[2], sb1[j])));
            float v2 = sb1n[j] - fmaf(sw1n[j*3], th[0], fmaf(sw1n[j*3+1], th[1], sw1n[j*3+2] * th[2]));
            x[at][3 + j] = fmaxf(u, 0.f) * a;
            x[at][6 + j] = fmaxf(v2, 0.f) * a;
        }
    }

    // ---- layer-2 accumulators ----
    unsigned long long acc2[3][8];
#pragma unroll
    for (int q = 0; q < 8; q++) {
        unsigned long long bb = pack2(sb2b[2*q], sb2b[2*q+1]);
#pragma unroll
        for (int at = 0; at < 3; at++) acc2[at][q] = bb;
    }

    // ---- layer 1: four 8-output tiles, fused into layer 2 ----
#pragma unroll
    for (int jt = 0; jt < 4; jt++) {
        unsigned long long a1[3][4];
#pragma unroll
        for (int at = 0; at < 3; at++) {
            const float4* cv = (const float4*)(g_cvec + gk[at] * 32) + jt * 2;
            float4 c0 = cv[0], c1 = cv[1];
            a1[at][0] = pack2(c0.x, c0.y);
            a1[at][1] = pack2(c0.z, c0.w);
            a1[at][2] = pack2(c1.x, c1.y);
            a1[at][3] = pack2(c1.z, c1.w);
        }
#pragma unroll
        for (int k = 0; k < 9; k++) {
            const ulonglong2* wr = (const ulonglong2*)(sW1t + k * 32 + jt * 8);
            ulonglong2 wa = wr[0], wb = wr[1];
#pragma unroll
            for (int at = 0; at < 3; at++) {
                unsigned long long xd = pack2(x[at][k], x[at][k]);
                a1[at][0] = fma2(wa.x, xd, a1[at][0]);
                a1[at][1] = fma2(wa.y, xd, a1[at][1]);
                a1[at][2] = fma2(wb.x, xd, a1[at][2]);
                a1[at][3] = fma2(wb.y, xd, a1[at][3]);
            }
        }
        // fuse: relu(h1) -> layer 2
#pragma unroll
        for (int p = 0; p < 4; p++) {
            float h1v[3][2];
#pragma unroll
            for (int at = 0; at < 3; at++) {
                float lo, hi;
                unpack2(a1[at][p], lo, hi);
                h1v[at][0] = fmaxf(lo, 0.f);
                h1v[at][1] = fmaxf(hi, 0.f);
            }
#pragma unroll
            for (int r = 0; r < 2; r++) {
                int k2i = jt * 8 + 2 * p + r;
                const ulonglong2* wr = (const ulonglong2*)(sW2t + k2i * 16);
                ulonglong2 wA = wr[0], wB = wr[1], wC = wr[2], wD = wr[3];
#pragma unroll
                for (int at = 0; at < 3; at++) {
                    unsigned long long hd = pack2(h1v[at][r], h1v[at][r]);
                    acc2[at][0] = fma2(wA.x, hd, acc2[at][0]);
                    acc2[at][1] = fma2(wA.y, hd, acc2[at][1]);
                    acc2[at][2] = fma2(wB.x, hd, acc2[at][2]);
                    acc2[at][3] = fma2(wB.y, hd, acc2[at][3]);
                    acc2[at][4] = fma2(wC.x, hd, acc2[at][4]);
                    acc2[at][5] = fma2(wC.y, hd, acc2[at][5]);
                    acc2[at][6] = fma2(wD.x, hd, acc2[at][6]);
                    acc2[at][7] = fma2(wD.y, hd, acc2[at][7]);
                }
            }
        }
    }

    // ---- layer 3 fused from acc2 (6 outputs: 3 u64 accs) ----
    unsigned long long acc3[3][3];
#pragma unroll
    for (int q = 0; q < 3; q++) {
        unsigned long long bb = pack2(sb2c[2*q], sb2c[2*q+1]);
#pragma unroll
        for (int at = 0; at < 3; at++) acc3[at][q] = bb;
    }
#pragma unroll
    for (int p = 0; p < 8; p++) {
        float h2v[3][2];
#pragma unroll
        for (int at = 0; at < 3; at++) {
            float lo, hi;
            unpack2(acc2[at][p], lo, hi);
            h2v[at][0] = leaky(lo);
            h2v[at][1] = leaky(hi);
        }
#pragma unroll
        for (int r = 0; r < 2; r++) {
            int k3i = 2 * p + r;
            const ulonglong2* wr = (const ulonglong2*)(sW3t + k3i * 8);
            ulonglong2 wab = wr[0];
            unsigned long long wc = *(const unsigned long long*)(sW3t + k3i * 8 + 4);
#pragma unroll
            for (int at = 0; at < 3; at++) {
                unsigned long long hd = pack2(h2v[at][r], h2v[at][r]);
                acc3[at][0] = fma2(wab.x, hd, acc3[at][0]);
                acc3[at][1] = fma2(wab.y, hd, acc3[at][1]);
                acc3[at][2] = fma2(wc,    hd, acc3[at][2]);
            }
        }
    }
    float hh[3][6];
#pragma unroll
    for (int at = 0; at < 3; at++) {
#pragma unroll
        for (int q = 0; q < 3; q++)
            unpack2(acc3[at][q], hh[at][2*q], hh[at][2*q+1]);
        if (at >= nval) {
#pragma unroll
            for (int k = 0; k < 6; k++) hh[at][k] = 0.f;
        }
    }

    // ---- segmented reduction: 3 sorted keys per thread ----
    int k0 = kk[0], k1 = kk[1], k2 = kk[2];

    // trailing-run sum (scanned across warp)
    float s[6];
#pragma unroll
    for (int k = 0; k < 6; k++) {
        float t = hh[2][k];
        if (k1 == k2) {
            t += hh[1][k];
            if (k0 == k2) t += hh[0][k];
        }
        s[k] = t;
    }

    const unsigned mask = 0xffffffffu;
    unsigned mseg = __match_any_sync(mask, k2);
    int head = __ffs(mseg) - 1;
#pragma unroll
    for (int d = 1; d < 32; d <<= 1) {
        bool take = (lane >= head + d);
#pragma unroll
        for (int k = 0; k < 6; k++) {
            float o = __shfl_up_sync(mask, s[k], d);
            if (take) s[k] += o;
        }
    }

    int kprev = __shfl_up_sync(mask, k2, 1);
    float sprev[6];
#pragma unroll
    for (int k = 0; k < 6; k++) sprev[k] = __shfl_up_sync(mask, s[k], 1);
    int knext0 = __shfl_down_sync(mask, k0, 1);

    // first run ends inside thread
    if (k0 >= 0 && k0 != k2) {
        bool carry = (lane > 0) && (kprev == k0);
#pragma unroll
        for (int k = 0; k < 6; k++) {
            float f = hh[0][k];
            if (k1 == k0) f += hh[1][k];
            if (carry) f += sprev[k];
            atomicAdd(&out[k0 * 6 + k], f);
        }
    }
    // middle run (fully inside thread)
    if (k1 >= 0 && k1 != k0 && k1 != k2) {
#pragma unroll
        for (int k = 0; k < 6; k++)
            atomicAdd(&out[k1 * 6 + k], hh[1][k]);
    }
    // trailing run flushed at segment tail
    bool tail = (lane == 31) || (knext0 != k2);
    if (k2 >= 0 && tail) {
#pragma unroll
        for (int k = 0; k < 6; k++)
            atomicAdd(&out[k2 * 6 + k], s[k]);
    }
}

extern "C" void kernel_launch(void* const* d_in, const int* in_sizes, int n_in,
                              void* d_out, int out_size)
{
    const float* atom_prop = (const float*)d_in[0];
    const float* pos       = (const float*)d_in[1];
    const float* cell      = (const float*)d_in[2];
    const int*   batch     = (const int*)d_in[3];
    const float* w0  = (const float*)d_in[4];
    const float* b0  = (const float*)d_in[5];
    const float* w1  = (const float*)d_in[6];
    const float* b1  = (const float*)d_in[7];
    const float* w1n = (const float*)d_in[8];
    const float* b1n = (const float*)d_in[9];
    const float* w2a = (const float*)d_in[10];
    const float* b2a = (const float*)d_in[11];
    const float* w2b = (const float*)d_in[12];
    const float* b2b = (const float*)d_in[13];
    const float* w2c = (const float*)d_in[14];
    const float* b2c = (const float*)d_in[15];
    float* out = (float*)d_out;

    int n = in_sizes[3];        // N_ATOMS
    int S = in_sizes[2] / 9;    // N_STRUCT

    precompute_kernel<<<(S + 7) / 8, 256>>>(cell, w2a, b2a, out, S);
    int atomsPerBlock = 128 * 3;
    atom_kernel<<<(n + atomsPerBlock - 1) / atomsPerBlock, 128>>>(
        atom_prop, pos, batch, w0, b0, w1, b1, w1n, b1n,
        w2a, w2b, b2b, w2c, b2c, out, n);
}

// round 10
// speedup vs baseline: 1.3113x; 1.3113x over previous
#include <cuda_runtime.h>

#define N_STRUCT_MAX 16384

__device__ __align__(16) float g_cinv[N_STRUCT_MAX * 12];
__device__ __align__(16) float g_cvec[N_STRUCT_MAX * 32];

// staging for transposed weights -> copied into __constant__ between kernels
__device__ unsigned long long g_stageW[459];
__device__ float g_stageF[64];

// W1 [0,144): [k][p] pair (w2a[2p][k], w2a[2p+1][k])  k<9,  p<16
// W2 [144,400): [k][q] pair (w2b[2q][k], w2b[2q+1][k]) k<32, q<8
// W3 [400,448): [k][q] pair (w2c[2q][k], w2c[2q+1][k]) k<16, q<3
// B2 [448,456), B3 [456,459)
__constant__ unsigned long long c_W[459];
__constant__ float c_F[64];   // w0[9] w1[9] w1n[9] b0[3] b1[3] b1n[3]

#define W1C(k,p) c_W[(k)*16+(p)]
#define W2C(k,q) c_W[144+(k)*8+(q)]
#define W3C(k,q) c_W[400+(k)*3+(q)]
#define B2C(q)   c_W[448+(q)]
#define B3C(q)   c_W[456+(q)]

__device__ __forceinline__ float leaky(float x) { return fmaxf(x, 0.01f * x); }

__device__ __forceinline__ unsigned long long pack2(float lo, float hi) {
    unsigned long long r;
    asm("mov.b64 %0, {%1, %2};" : "=l"(r) : "f"(lo), "f"(hi));
    return r;
}
__device__ __forceinline__ void unpack2(unsigned long long v, float& lo, float& hi) {
    asm("mov.b64 {%0, %1}, %2;" : "=f"(lo), "=f"(hi) : "l"(v));
}
__device__ __forceinline__ unsigned long long fma2(unsigned long long a, unsigned long long b,
                                                   unsigned long long c) {
    unsigned long long d;
    asm("fma.rn.f32x2 %0, %1, %2, %3;" : "=l"(d) : "l"(a), "l"(b), "l"(c));
    return d;
}

// One warp per structure; block 0 additionally stages transposed weights.
__global__ __launch_bounds__(256) void precompute_kernel(
    const float* __restrict__ cell,
    const float* __restrict__ w2a,
    const float* __restrict__ b2a,
    const float* __restrict__ w0, const float* __restrict__ b0,
    const float* __restrict__ w1, const float* __restrict__ b1,
    const float* __restrict__ w1n, const float* __restrict__ b1n,
    const float* __restrict__ w2b, const float* __restrict__ b2b,
    const float* __restrict__ w2c, const float* __restrict__ b2c,
    float* __restrict__ out, int S)
{
    __shared__ float sW[81 * 32];  // [t][j] = w2a[j*90+9+t]
    int tid = threadIdx.x;
    for (int i = tid; i < 81 * 32; i += blockDim.x) {
        int t = i >> 5, j = i & 31;
        sW[i] = w2a[j * 90 + 9 + t];
    }
    __syncthreads();

    if (blockIdx.x == 0) {
        // stage transposed weight pairs
        for (int i = tid; i < 144; i += blockDim.x) {
            int k = i >> 4, p = i & 15;
            g_stageW[i] = pack2(w2a[(2*p) * 90 + k], w2a[(2*p+1) * 90 + k]);
        }
        for (int i = tid; i < 256; i += blockDim.x) {
            int k = i >> 3, q = i & 7;
            g_stageW[144 + i] = pack2(w2b[(2*q) * 32 + k], w2b[(2*q+1) * 32 + k]);
        }
        for (int i = tid; i < 48; i += blockDim.x) {
            int k = i / 3, q = i - 3 * k;
            g_stageW[400 + i] = pack2(w2c[(2*q) * 16 + k], w2c[(2*q+1) * 16 + k]);
        }
        if (tid < 8) g_stageW[448 + tid] = pack2(b2b[2*tid], b2b[2*tid+1]);
        else if (tid < 11) { int q = tid - 8; g_stageW[456 + q] = pack2(b2c[2*q], b2c[2*q+1]); }
        else if (tid >= 32 && tid < 96) {
            int t = tid - 32;
            float v = 0.f;
            if (t < 9)       v = w0[t];
            else if (t < 18) v = w1[t - 9];
            else if (t < 27) v = w1n[t - 18];
            else if (t < 30) v = b0[t - 27];
            else if (t < 33) v = b1[t - 30];
            else if (t < 36) v = b1n[t - 33];
            g_stageF[t] = v;
        }
    }

    int warpId = tid >> 5;
    int lane = tid & 31;
    int s = blockIdx.x * 8 + warpId;
    if (s >= S) return;

    float m[9];
#pragma unroll
    for (int i = 0; i < 9; i++) m[i] = __ldg(cell + s * 9 + i);

    float acc = b2a[lane];
#pragma unroll
    for (int p = 0; p < 9; p++) {
        float mp = m[p];
#pragma unroll
        for (int q = 0; q < 9; q++)
            acc = fmaf(sW[(p * 9 + q) * 32 + lane], mp * m[q], acc);
    }
    g_cvec[s * 32 + lane] = acc;

    if (lane < 6) out[s * 6 + lane] = 0.f;

    if (lane == 0) {
        float c00 = m[4] * m[8] - m[5] * m[7];
        float c01 = m[5] * m[6] - m[3] * m[8];
        float c02 = m[3] * m[7] - m[4] * m[6];
        float det = m[0] * c00 + m[1] * c01 + m[2] * c02;
        float id = 1.f / det;
        float4* o = (float4*)(g_cinv + s * 12);
        float4 r0, r1, r2;
        r0.x = c00 * id;
        r0.y = (m[2] * m[7] - m[1] * m[8]) * id;
        r0.z = (m[1] * m[5] - m[2] * m[4]) * id;
        r0.w = c01 * id;
        r1.x = (m[0] * m[8] - m[2] * m[6]) * id;
        r1.y = (m[2] * m[3] - m[0] * m[5]) * id;
        r1.z = c02 * id;
        r1.w = (m[1] * m[6] - m[0] * m[7]) * id;
        r2.x = (m[0] * m[4] - m[1] * m[3]) * id;
        r2.y = 0.f; r2.z = 0.f; r2.w = 0.f;
        o[0] = r0; o[1] = r1; o[2] = r2;
    }
}

// 2 atoms per thread; all weights in __constant__ (uniform port, no smem).
__global__ void __launch_bounds__(128, 6) atom_kernel(
    const float* __restrict__ atom_prop, const float* __restrict__ pos,
    const int* __restrict__ batch,
    float* __restrict__ out, int n)
{
    int tid = threadIdx.x;
    int lane = tid & 31;
    int i0 = (blockIdx.x * blockDim.x + tid) * 2;
    int i1 = i0 + 1;
    bool v0 = i0 < n, v1 = i1 < n;
    int b0i, b1i;
    if (v1) {
        int2 bb = *(const int2*)(batch + i0);
        b0i = bb.x; b1i = bb.y;
    } else if (v0) {
        b0i = batch[i0]; b1i = b0i;
    } else {
        b0i = -1; b1i = -1;
    }

    float hA[6], hB[6];
#pragma unroll
    for (int k = 0; k < 6; k++) { hA[k] = 0.f; hB[k] = 0.f; }

    if (v0) {
        // ---- head ----
        const float2* pp = (const float2*)(pos + 3 * i0);
        float2 q0 = pp[0], q1 = pp[1], q2 = v1 ? pp[2] : make_float2(0.f, 0.f);
        const float2* ap = (const float2*)(atom_prop + 3 * i0);
        float2 a0 = ap[0], a1 = ap[1], a2 = v1 ? ap[2] : make_float2(0.f, 0.f);

        float pA[3] = {q0.x, q0.y, q1.x};
        float pB[3] = {q1.y, q2.x, q2.y};
        float apA[3] = {a0.x, a0.y, a1.x};
        float apB[3] = {a1.y, a2.x, a2.y};

        float xA[9], xB[9];
#pragma unroll
        for (int at = 0; at < 2; at++) {
            int bb = at ? b1i : b0i;
            const float* P = at ? pB : pA;
            const float* AP = at ? apB : apA;
            float* X = at ? xB : xA;
            const float4* civ = (const float4*)(g_cinv + bb * 12);
            float4 c0 = civ[0], c1 = civ[1], c2 = civ[2];
            float ci[9] = {c0.x, c0.y, c0.z, c0.w, c1.x, c1.y, c1.z, c1.w, c2.x};
            float th[3];
#pragma unroll
            for (int e = 0; e < 3; e++) {
                float f = fmaf(P[0], ci[e], fmaf(P[1], ci[3 + e], P[2] * ci[6 + e]));
                th[e] = f - floorf(f) - 0.5f;
            }
            X[0] = AP[0]; X[1] = AP[1]; X[2] = AP[2];
#pragma unroll
            for (int j = 0; j < 3; j++) {
                float a = leaky(fmaf(c_F[j*3], AP[0], fmaf(c_F[j*3+1], AP[1], fmaf(c_F[j*3+2], AP[2], c_F[27+j]))));
                float u = fmaf(c_F[9+j*3], th[0], fmaf(c_F[9+j*3+1], th[1], fmaf(c_F[9+j*3+2], th[2], c_F[30+j])));
                float v = c_F[33+j] - fmaf(c_F[18+j*3], th[0], fmaf(c_F[18+j*3+1], th[1], c_F[18+j*3+2] * th[2]));
                X[3 + j] = fmaxf(u, 0.f) * a;
                X[6 + j] = fmaxf(v, 0.f) * a;
            }
        }

        // ---- layer-2 accumulators ----
        unsigned long long acc2A[8], acc2B[8];
#pragma unroll
        for (int q = 0; q < 8; q++) {
            unsigned long long bb = B2C(q);
            acc2A[q] = bb; acc2B[q] = bb;
        }

        // ---- layer 1: four 8-output tiles, fused into layer 2 ----
#pragma unroll
        for (int jt = 0; jt < 4; jt++) {
            unsigned long long a1A[4], a1B[4];
            const float4* cvA = (const float4*)(g_cvec + b0i * 32) + jt * 2;
            const float4* cvB = (const float4*)(g_cvec + b1i * 32) + jt * 2;
#pragma unroll
            for (int q = 0; q < 2; q++) {
                float4 ca = cvA[q], cb = cvB[q];
                a1A[2*q]   = pack2(ca.x, ca.y);
                a1A[2*q+1] = pack2(ca.z, ca.w);
                a1B[2*q]   = pack2(cb.x, cb.y);
                a1B[2*q+1] = pack2(cb.z, cb.w);
            }
#pragma unroll
            for (int k = 0; k < 9; k++) {
                unsigned long long xa = pack2(xA[k], xA[k]);
                unsigned long long xb = pack2(xB[k], xB[k]);
#pragma unroll
                for (int q = 0; q < 4; q++) {
                    unsigned long long w = W1C(k, jt * 4 + q);
                    a1A[q] = fma2(w, xa, a1A[q]);
                    a1B[q] = fma2(w, xb, a1B[q]);
                }
            }
            // fuse: relu(h1) -> layer 2
#pragma unroll
            for (int p = 0; p < 4; p++) {
                float lA0, lA1, lB0, lB1;
                unpack2(a1A[p], lA0, lA1);
                unpack2(a1B[p], lB0, lB1);
                lA0 = fmaxf(lA0, 0.f); lA1 = fmaxf(lA1, 0.f);
                lB0 = fmaxf(lB0, 0.f); lB1 = fmaxf(lB1, 0.f);
#pragma unroll
                for (int r = 0; r < 2; r++) {
                    int k2i = jt * 8 + 2 * p + r;
                    unsigned long long xa = pack2(r ? lA1 : lA0, r ? lA1 : lA0);
                    unsigned long long xb = pack2(r ? lB1 : lB0, r ? lB1 : lB0);
#pragma unroll
                    for (int q = 0; q < 8; q++) {
                        unsigned long long w = W2C(k2i, q);
                        acc2A[q] = fma2(w, xa, acc2A[q]);
                        acc2B[q] = fma2(w, xb, acc2B[q]);
                    }
                }
            }
        }

        // ---- layer 3 fused from acc2 (6 outputs: 3 u64 accs) ----
        unsigned long long acc3A[3], acc3B[3];
#pragma unroll
        for (int q = 0; q < 3; q++) {
            unsigned long long bb = B3C(q);
            acc3A[q] = bb; acc3B[q] = bb;
        }
#pragma unroll
        for (int p = 0; p < 8; p++) {
            float lA0, lA1, lB0, lB1;
            unpack2(acc2A[p], lA0, lA1);
            unpack2(acc2B[p], lB0, lB1);
            lA0 = leaky(lA0); lA1 = leaky(lA1);
            lB0 = leaky(lB0); lB1 = leaky(lB1);
#pragma unroll
            for (int r = 0; r < 2; r++) {
                int k3i = 2 * p + r;
                unsigned long long xa = pack2(r ? lA1 : lA0, r ? lA1 : lA0);
                unsigned long long xb = pack2(r ? lB1 : lB0, r ? lB1 : lB0);
#pragma unroll
                for (int q = 0; q < 3; q++) {
                    unsigned long long w = W3C(k3i, q);
                    acc3A[q] = fma2(w, xa, acc3A[q]);
                    acc3B[q] = fma2(w, xb, acc3B[q]);
                }
            }
        }
#pragma unroll
        for (int p = 0; p < 3; p++) {
            unpack2(acc3A[p], hA[2*p], hA[2*p+1]);
            unpack2(acc3B[p], hB[2*p], hB[2*p+1]);
        }
        if (!v1) {
#pragma unroll
            for (int k = 0; k < 6; k++) hB[k] = 0.f;
        }
    }

    // ---- segmented reduction over sorted batch (2 atoms/thread) ----
    float vscan[6];
    bool split = (b0i != b1i);
#pragma unroll
    for (int k = 0; k < 6; k++) vscan[k] = split ? hB[k] : (hA[k] + hB[k]);

    const unsigned mask = 0xffffffffu;
    unsigned mseg = __match_any_sync(mask, b1i);
    int head = __ffs(mseg) - 1;
#pragma unroll
    for (int d = 1; d < 32; d <<= 1) {
        bool take = (lane >= head + d);
#pragma unroll
        for (int k = 0; k < 6; k++) {
            float o = __shfl_up_sync(mask, vscan[k], d);
            if (take) vscan[k] += o;
        }
    }

    int bprev = __shfl_up_sync(mask, b1i, 1);
    float sprev[6];
#pragma unroll
    for (int k = 0; k < 6; k++) sprev[k] = __shfl_up_sync(mask, vscan[k], 1);
    int bnext0 = __shfl_down_sync(mask, b0i, 1);

    if (split && b0i >= 0) {
        bool carry = (lane > 0) && (bprev == b0i);
#pragma unroll
        for (int k = 0; k < 6; k++) {
            float t = hA[k] + (carry ? sprev[k] : 0.f);
            atomicAdd(&out[b0i * 6 + k], t);
        }
    }
    bool tail = (lane == 31) || (bnext0 != b1i);
    if (b1i >= 0 && tail) {
#pragma unroll
        for (int k = 0; k < 6; k++) atomicAdd(&out[b1i * 6 + k], vscan[k]);
    }
}

extern "C" void kernel_launch(void* const* d_in, const int* in_sizes, int n_in,
                              void* d_out, int out_size)
{
    const float* atom_prop = (const float*)d_in[0];
    const float* pos       = (const float*)d_in[1];
    const float* cell      = (const float*)d_in[2];
    const int*   batch     = (const int*)d_in[3];
    const float* w0  = (const float*)d_in[4];
    const float* b0  = (const float*)d_in[5];
    const float* w1  = (const float*)d_in[6];
    const float* b1  = (const float*)d_in[7];
    const float* w1n = (const float*)d_in[8];
    const float* b1n = (const float*)d_in[9];
    const float* w2a = (const float*)d_in[10];
    const float* b2a = (const float*)d_in[11];
    const float* w2b = (const float*)d_in[12];
    const float* b2b = (const float*)d_in[13];
    const float* w2c = (const float*)d_in[14];
    const float* b2c = (const float*)d_in[15];
    float* out = (float*)d_out;

    int n = in_sizes[3];        // N_ATOMS
    int S = in_sizes[2] / 9;    // N_STRUCT

    void *dW = nullptr, *dF = nullptr, *sW = nullptr, *sF = nullptr;
    cudaGetSymbolAddress(&dW, c_W);
    cudaGetSymbolAddress(&dF, c_F);
    cudaGetSymbolAddress(&sW, g_stageW);
    cudaGetSymbolAddress(&sF, g_stageF);

    precompute_kernel<<<(S + 7) / 8, 256>>>(cell, w2a, b2a,
                                            w0, b0, w1, b1, w1n, b1n,
                                            w2b, b2b, w2c, b2c, out, S);
    cudaMemcpyAsync(dW, sW, 459 * sizeof(unsigned long long),
                    cudaMemcpyDeviceToDevice, 0);
    cudaMemcpyAsync(dF, sF, 64 * sizeof(float),
                    cudaMemcpyDeviceToDevice, 0);
    atom_kernel<<<(n + 255) / 256, 128>>>(atom_prop, pos, batch, out, n);
}

// round 12
// speedup vs baseline: 1.4560x; 1.1103x over previous
#include <cuda_runtime.h>

#define N_STRUCT_MAX 16384

__device__ __align__(16) float g_cinv[N_STRUCT_MAX * 12];
__device__ __align__(16) float g_cvec[N_STRUCT_MAX * 32];

// W1 [0,144): [k][p] pair (w2a[2p][k], w2a[2p+1][k])  k<9,  p<16
// W2 [144,400): [k][q] pair (w2b[2q][k], w2b[2q+1][k]) k<32, q<8
// W3 [400,448): [k][q] pair (w2c[2q][k], w2c[2q+1][k]) k<16, q<3
// B2 [448,456), B3 [456,459)
// F: w0[9] w1[9] w1n[9] b0[3] b1[3] b1n[3] (+pad)
struct ConstBlob {
    unsigned long long W[459];
    float F[40];
};

__device__ ConstBlob g_stage;     // staged by precompute kernel
__constant__ ConstBlob c_blob;    // single D2D memcpy from g_stage

#define W1C(k,p) c_blob.W[(k)*16+(p)]
#define W2C(k,q) c_blob.W[144+(k)*8+(q)]
#define W3C(k,q) c_blob.W[400+(k)*3+(q)]
#define B2C(q)   c_blob.W[448+(q)]
#define B3C(q)   c_blob.W[456+(q)]
#define CF(i)    c_blob.F[(i)]

__device__ __forceinline__ float leaky(float x) { return fmaxf(x, 0.01f * x); }

__device__ __forceinline__ unsigned long long pack2(float lo, float hi) {
    unsigned long long r;
    asm("mov.b64 %0, {%1, %2};" : "=l"(r) : "f"(lo), "f"(hi));
    return r;
}
__device__ __forceinline__ void unpack2(unsigned long long v, float& lo, float& hi) {
    asm("mov.b64 {%0, %1}, %2;" : "=f"(lo), "=f"(hi) : "l"(v));
}
__device__ __forceinline__ unsigned long long fma2(unsigned long long a, unsigned long long b,
                                                   unsigned long long c) {
    unsigned long long d;
    asm("fma.rn.f32x2 %0, %1, %2, %3;" : "=l"(d) : "l"(a), "l"(b), "l"(c));
    return d;
}

// One warp per structure; block 0 additionally stages transposed weights.
__global__ __launch_bounds__(256) void precompute_kernel(
    const float* __restrict__ cell,
    const float* __restrict__ w2a,
    const float* __restrict__ b2a,
    const float* __restrict__ w0, const float* __restrict__ b0,
    const float* __restrict__ w1, const float* __restrict__ b1,
    const float* __restrict__ w1n, const float* __restrict__ b1n,
    const float* __restrict__ w2b, const float* __restrict__ b2b,
    const float* __restrict__ w2c, const float* __restrict__ b2c,
    float* __restrict__ out, int S)
{
    __shared__ float sW[81 * 32];  // [t][j] = w2a[j*90+9+t]
    int tid = threadIdx.x;
    for (int i = tid; i < 81 * 32; i += blockDim.x) {
        int t = i >> 5, j = i & 31;
        sW[i] = w2a[j * 90 + 9 + t];
    }
    __syncthreads();

    if (blockIdx.x == 0) {
        for (int i = tid; i < 144; i += blockDim.x) {
            int k = i >> 4, p = i & 15;
            g_stage.W[i] = pack2(w2a[(2*p) * 90 + k], w2a[(2*p+1) * 90 + k]);
        }
        for (int i = tid; i < 256; i += blockDim.x) {
            int k = i >> 3, q = i & 7;
            g_stage.W[144 + i] = pack2(w2b[(2*q) * 32 + k], w2b[(2*q+1) * 32 + k]);
        }
        for (int i = tid; i < 48; i += blockDim.x) {
            int k = i / 3, q = i - 3 * k;
            g_stage.W[400 + i] = pack2(w2c[(2*q) * 16 + k], w2c[(2*q+1) * 16 + k]);
        }
        if (tid < 8) g_stage.W[448 + tid] = pack2(b2b[2*tid], b2b[2*tid+1]);
        else if (tid < 11) { int q = tid - 8; g_stage.W[456 + q] = pack2(b2c[2*q], b2c[2*q+1]); }
        else if (tid >= 32 && tid < 72) {
            int t = tid - 32;
            float v = 0.f;
            if (t < 9)       v = w0[t];
            else if (t < 18) v = w1[t - 9];
            else if (t < 27) v = w1n[t - 18];
            else if (t < 30) v = b0[t - 27];
            else if (t < 33) v = b1[t - 30];
            else if (t < 36) v = b1n[t - 33];
            g_stage.F[t] = v;
        }
    }

    int warpId = tid >> 5;
    int lane = tid & 31;
    int s = blockIdx.x * 8 + warpId;
    if (s >= S) return;

    float m[9];
#pragma unroll
    for (int i = 0; i < 9; i++) m[i] = __ldg(cell + s * 9 + i);

    float acc = b2a[lane];
#pragma unroll
    for (int p = 0; p < 9; p++) {
        float mp = m[p];
#pragma unroll
        for (int q = 0; q < 9; q++)
            acc = fmaf(sW[(p * 9 + q) * 32 + lane], mp * m[q], acc);
    }
    g_cvec[s * 32 + lane] = acc;

    if (lane < 6) out[s * 6 + lane] = 0.f;

    if (lane == 0) {
        float c00 = m[4] * m[8] - m[5] * m[7];
        float c01 = m[5] * m[6] - m[3] * m[8];
        float c02 = m[3] * m[7] - m[4] * m[6];
        float det = m[0] * c00 + m[1] * c01 + m[2] * c02;
        float id = 1.f / det;
        float4* o = (float4*)(g_cinv + s * 12);
        float4 r0, r1, r2;
        r0.x = c00 * id;
        r0.y = (m[2] * m[7] - m[1] * m[8]) * id;
        r0.z = (m[1] * m[5] - m[2] * m[4]) * id;
        r0.w = c01 * id;
        r1.x = (m[0] * m[8] - m[2] * m[6]) * id;
        r1.y = (m[2] * m[3] - m[0] * m[5]) * id;
        r1.z = c02 * id;
        r1.w = (m[1] * m[6] - m[0] * m[7]) * id;
        r2.x = (m[0] * m[4] - m[1] * m[3]) * id;
        r2.y = 0.f; r2.z = 0.f; r2.w = 0.f;
        o[0] = r0; o[1] = r1; o[2] = r2;
    }
}

// 2 atoms per thread; weights in __constant__ (uniform port); pre-packed x.
__global__ void __launch_bounds__(128, 5) atom_kernel(
    const float* __restrict__ atom_prop, const float* __restrict__ pos,
    const int* __restrict__ batch,
    float* __restrict__ out, int n)
{
    int tid = threadIdx.x;
    int lane = tid & 31;
    int i0 = (blockIdx.x * blockDim.x + tid) * 2;
    int i1 = i0 + 1;
    bool v0 = i0 < n, v1 = i1 < n;
    int b0i, b1i;
    if (v1) {
        int2 bb = *(const int2*)(batch + i0);
        b0i = bb.x; b1i = bb.y;
    } else if (v0) {
        b0i = batch[i0]; b1i = b0i;
    } else {
        b0i = -1; b1i = -1;
    }

    float hA[6], hB[6];
#pragma unroll
    for (int k = 0; k < 6; k++) { hA[k] = 0.f; hB[k] = 0.f; }

    if (v0) {
        // ---- head ----
        const float2* pp = (const float2*)(pos + 3 * i0);
        float2 q0 = pp[0], q1 = pp[1], q2 = v1 ? pp[2] : make_float2(0.f, 0.f);
        const float2* ap = (const float2*)(atom_prop + 3 * i0);
        float2 a0 = ap[0], a1 = ap[1], a2 = v1 ? ap[2] : make_float2(0.f, 0.f);

        float pA[3] = {q0.x, q0.y, q1.x};
        float pB[3] = {q1.y, q2.x, q2.y};
        float apA[3] = {a0.x, a0.y, a1.x};
        float apB[3] = {a1.y, a2.x, a2.y};

        // packed per-atom feature vectors (each u64 holds (x,x) broadcast pair)
        unsigned long long xdA[9], xdB[9];
#pragma unroll
        for (int at = 0; at < 2; at++) {
            int bb = at ? b1i : b0i;
            const float* P = at ? pB : pA;
            const float* AP = at ? apB : apA;
            unsigned long long* XD = at ? xdB : xdA;
            const float4* civ = (const float4*)(g_cinv + bb * 12);
            float4 c0 = civ[0], c1 = civ[1], c2 = civ[2];
            float ci[9] = {c0.x, c0.y, c0.z, c0.w, c1.x, c1.y, c1.z, c1.w, c2.x};
            float th[3];
#pragma unroll
            for (int e = 0; e < 3; e++) {
                float f = fmaf(P[0], ci[e], fmaf(P[1], ci[3 + e], P[2] * ci[6 + e]));
                th[e] = f - floorf(f) - 0.5f;
            }
            XD[0] = pack2(AP[0], AP[0]);
            XD[1] = pack2(AP[1], AP[1]);
            XD[2] = pack2(AP[2], AP[2]);
#pragma unroll
            for (int j = 0; j < 3; j++) {
                float a = leaky(fmaf(CF(j*3), AP[0], fmaf(CF(j*3+1), AP[1], fmaf(CF(j*3+2), AP[2], CF(27+j)))));
                float u = fmaf(CF(9+j*3), th[0], fmaf(CF(9+j*3+1), th[1], fmaf(CF(9+j*3+2), th[2], CF(30+j))));
                float v = CF(33+j) - fmaf(CF(18+j*3), th[0], fmaf(CF(18+j*3+1), th[1], CF(18+j*3+2) * th[2]));
                float t1 = fmaxf(u, 0.f) * a;
                float t2 = fmaxf(v, 0.f) * a;
                XD[3 + j] = pack2(t1, t1);
                XD[6 + j] = pack2(t2, t2);
            }
        }

        // ---- layer-2 accumulators ----
        unsigned long long acc2A[8], acc2B[8];
#pragma unroll
        for (int q = 0; q < 8; q++) {
            unsigned long long bb = B2C(q);
            acc2A[q] = bb; acc2B[q] = bb;
        }

        // ---- layer 1: four 8-output tiles, fused into layer 2 ----
#pragma unroll
        for (int jt = 0; jt < 4; jt++) {
            unsigned long long a1A[4], a1B[4];
            const float4* cvA = (const float4*)(g_cvec + b0i * 32) + jt * 2;
            const float4* cvB = (const float4*)(g_cvec + b1i * 32) + jt * 2;
#pragma unroll
            for (int q = 0; q < 2; q++) {
                float4 ca = cvA[q], cb = cvB[q];
                a1A[2*q]   = pack2(ca.x, ca.y);
                a1A[2*q+1] = pack2(ca.z, ca.w);
                a1B[2*q]   = pack2(cb.x, cb.y);
                a1B[2*q+1] = pack2(cb.z, cb.w);
            }
#pragma unroll
            for (int k = 0; k < 9; k++) {
#pragma unroll
                for (int q = 0; q < 4; q++) {
                    unsigned long long w = W1C(k, jt * 4 + q);
                    a1A[q] = fma2(w, xdA[k], a1A[q]);
                    a1B[q] = fma2(w, xdB[k], a1B[q]);
                }
            }
            // fuse: relu(h1) -> layer 2
#pragma unroll
            for (int p = 0; p < 4; p++) {
                float lA0, lA1, lB0, lB1;
                unpack2(a1A[p], lA0, lA1);
                unpack2(a1B[p], lB0, lB1);
                lA0 = fmaxf(lA0, 0.f); lA1 = fmaxf(lA1, 0.f);
                lB0 = fmaxf(lB0, 0.f); lB1 = fmaxf(lB1, 0.f);
#pragma unroll
                for (int r = 0; r < 2; r++) {
                    int k2i = jt * 8 + 2 * p + r;
                    unsigned long long xa = pack2(r ? lA1 : lA0, r ? lA1 : lA0);
                    unsigned long long xb = pack2(r ? lB1 : lB0, r ? lB1 : lB0);
#pragma unroll
                    for (int q = 0; q < 8; q++) {
                        unsigned long long w = W2C(k2i, q);
                        acc2A[q] = fma2(w, xa, acc2A[q]);
                        acc2B[q] = fma2(w, xb, acc2B[q]);
                    }
                }
            }
        }

        // ---- layer 3 fused from acc2 (6 outputs: 3 u64 accs) ----
        unsigned long long acc3A[3], acc3B[3];
#pragma unroll
        for (int q = 0; q < 3; q++) {
            unsigned long long bb = B3C(q);
            acc3A[q] = bb; acc3B[q] = bb;
        }
#pragma unroll
        for (int p = 0; p < 8; p++) {
            float lA0, lA1, lB0, lB1;
            unpack2(acc2A[p], lA0, lA1);
            unpack2(acc2B[p], lB0, lB1);
            lA0 = leaky(lA0); lA1 = leaky(lA1);
            lB0 = leaky(lB0); lB1 = leaky(lB1);
#pragma unroll
            for (int r = 0; r < 2; r++) {
                int k3i = 2 * p + r;
                unsigned long long xa = pack2(r ? lA1 : lA0, r ? lA1 : lA0);
                unsigned long long xb = pack2(r ? lB1 : lB0, r ? lB1 : lB0);
#pragma unroll
                for (int q = 0; q < 3; q++) {
                    unsigned long long w = W3C(k3i, q);
                    acc3A[q] = fma2(w, xa, acc3A[q]);
                    acc3B[q] = fma2(w, xb, acc3B[q]);
                }
            }
        }
#pragma unroll
        for (int p = 0; p < 3; p++) {
            unpack2(acc3A[p], hA[2*p], hA[2*p+1]);
            unpack2(acc3B[p], hB[2*p], hB[2*p+1]);
        }
        if (!v1) {
#pragma unroll
            for (int k = 0; k < 6; k++) hB[k] = 0.f;
        }
    }

    // ---- segmented reduction over sorted batch (2 atoms/thread) ----
    float vscan[6];
    bool split = (b0i != b1i);
#pragma unroll
    for (int k = 0; k < 6; k++) vscan[k] = split ? hB[k] : (hA[k] + hB[k]);

    const unsigned mask = 0xffffffffu;
    unsigned mseg = __match_any_sync(mask, b1i);
    int head = __ffs(mseg) - 1;
#pragma unroll
    for (int d = 1; d < 32; d <<= 1) {
        bool take = (lane >= head + d);
#pragma unroll
        for (int k = 0; k < 6; k++) {
            float o = __shfl_up_sync(mask, vscan[k], d);
            if (take) vscan[k] += o;
        }
    }

    int bprev = __shfl_up_sync(mask, b1i, 1);
    float sprev[6];
#pragma unroll
    for (int k = 0; k < 6; k++) sprev[k] = __shfl_up_sync(mask, vscan[k], 1);
    int bnext0 = __shfl_down_sync(mask, b0i, 1);

    if (split && b0i >= 0) {
        bool carry = (lane > 0) && (bprev == b0i);
#pragma unroll
        for (int k = 0; k < 6; k++) {
            float t = hA[k] + (carry ? sprev[k] : 0.f);
            atomicAdd(&out[b0i * 6 + k], t);
        }
    }
    bool tail = (lane == 31) || (bnext0 != b1i);
    if (b1i >= 0 && tail) {
#pragma unroll
        for (int k = 0; k < 6; k++) atomicAdd(&out[b1i * 6 + k], vscan[k]);
    }
}

extern "C" void kernel_launch(void* const* d_in, const int* in_sizes, int n_in,
                              void* d_out, int out_size)
{
    const float* atom_prop = (const float*)d_in[0];
    const float* pos       = (const float*)d_in[1];
    const float* cell      = (const float*)d_in[2];
    const int*   batch     = (const int*)d_in[3];
    const float* w0  = (const float*)d_in[4];
    const float* b0  = (const float*)d_in[5];
    const float* w1  = (const float*)d_in[6];
    const float* b1  = (const float*)d_in[7];
    const float* w1n = (const float*)d_in[8];
    const float* b1n = (const float*)d_in[9];
    const float* w2a = (const float*)d_in[10];
    const float* b2a = (const float*)d_in[11];
    const float* w2b = (const float*)d_in[12];
    const float* b2b = (const float*)d_in[13];
    const float* w2c = (const float*)d_in[14];
    const float* b2c = (const float*)d_in[15];
    float* out = (float*)d_out;

    int n = in_sizes[3];        // N_ATOMS
    int S = in_sizes[2] / 9;    // N_STRUCT

    void *dC = nullptr, *sC = nullptr;
    cudaGetSymbolAddress(&dC, c_blob);
    cudaGetSymbolAddress(&sC, g_stage);

    precompute_kernel<<<(S + 7) / 8, 256>>>(cell, w2a, b2a,
                                            w0, b0, w1, b1, w1n, b1n,
                                            w2b, b2b, w2c, b2c, out, S);
    cudaMemcpyAsync(dC, sC, sizeof(ConstBlob), cudaMemcpyDeviceToDevice, 0);
    atom_kernel<<<(n + 255) / 256, 128>>>(atom_prop, pos, batch, out, n);
}